// round 6
// baseline (speedup 1.0000x reference)
#include <cuda_runtime.h>
#include <cstdint>

#define MAXN 50000
#define MAXE 800000

// Device scratch (allocation-free rule: __device__ globals)
__device__ float g_diag[(size_t)MAXN * 16];   // per-node Gram accumulators
__device__ float g_invs[(size_t)MAXN * 16];   // per-node inverse sqrt matrices
__device__ float g_triu[(size_t)MAXE * 16];   // per-edge M1^T M2

// float4 helpers
__device__ __forceinline__ float4 f4_fma(float s, float4 v, float4 acc) {
    acc.x = fmaf(s, v.x, acc.x); acc.y = fmaf(s, v.y, acc.y);
    acc.z = fmaf(s, v.z, acc.z); acc.w = fmaf(s, v.w, acc.w);
    return acc;
}
__device__ __forceinline__ float pick(float4 v, int a) {
    float r = v.x;
    r = (a == 1) ? v.y : r;
    r = (a == 2) ? v.z : r;
    r = (a == 3) ? v.w : r;
    return r;
}
__device__ __forceinline__ float4 shfl4(float4 v, int src) {
    float4 r;
    r.x = __shfl_sync(0xffffffffu, v.x, src, 4);
    r.y = __shfl_sync(0xffffffffu, v.y, src, 4);
    r.z = __shfl_sync(0xffffffffu, v.z, src, 4);
    r.w = __shfl_sync(0xffffffffu, v.w, src, 4);
    return r;
}
__device__ __forceinline__ float4 clip4(float4 v) {
    return make_float4(fminf(fmaxf(v.x, -1.f), 1.f),
                       fminf(fmaxf(v.y, -1.f), 1.f),
                       fminf(fmaxf(v.z, -1.f), 1.f),
                       fminf(fmaxf(v.w, -1.f), 1.f));
}
__device__ __forceinline__ float4 neg4(float4 v) {
    return make_float4(-v.x, -v.y, -v.z, -v.w);
}

// ---------------------------------------------------------------------------
// Kernel 0: zero the diag accumulators
// ---------------------------------------------------------------------------
__global__ void k_zero_diag(int n4) {
    int i = blockIdx.x * blockDim.x + threadIdx.x;
    if (i < n4) reinterpret_cast<float4*>(g_diag)[i] = make_float4(0.f, 0.f, 0.f, 0.f);
}

// ---------------------------------------------------------------------------
// Kernel 1 (quad-per-edge, shuffle-shared): thread (e, a) loads only row a of
// M1 and M2; other rows via quad shuffles.
//   C1 = M1^T M1 -> atomicAdd diag[row];  C2 = M2^T M2 -> atomicAdd diag[col]
//   P  = M1^T M2 -> streaming store g_triu[e] row a
// ---------------------------------------------------------------------------
__global__ void k_edges(const float* __restrict__ maps,
                        const int*   __restrict__ ei0,
                        int E) {
    int t = blockIdx.x * blockDim.x + threadIdx.x;
    int e = t >> 2, a = t & 3;
    if (e >= E) return;

    const float4* mp = reinterpret_cast<const float4*>(maps);
    float4 m1row = __ldcs(mp + (size_t)e * 4 + a);
    float4 m2row = __ldcs(mp + ((size_t)E + e) * 4 + a);

    float4 c1 = make_float4(0.f, 0.f, 0.f, 0.f);
    float4 c2 = c1, p = c1;
#pragma unroll
    for (int k = 0; k < 4; k++) {
        float4 r1 = shfl4(m1row, k);     // M1 row k
        float4 r2 = shfl4(m2row, k);     // M2 row k
        float s1 = pick(r1, a);          // M1[k][a]
        float s2 = pick(r2, a);          // M2[k][a]
        c1 = f4_fma(s1, r1, c1);
        c2 = f4_fma(s2, r2, c2);
        p  = f4_fma(s1, r2, p);
    }

    int r = ei0[e];
    int c = ei0[E + e];

    atomicAdd(reinterpret_cast<float4*>(g_diag) + (size_t)r * 4 + a, c1);
    atomicAdd(reinterpret_cast<float4*>(g_diag) + (size_t)c * 4 + a, c2);
    __stcs(reinterpret_cast<float4*>(g_triu) + (size_t)e * 4 + a, p);
}

// ---------------------------------------------------------------------------
// Kernel 2 (quad-per-node, shuffle-shared): thread (n, a) owns row a.
//   A = diag[n] + I; Z = A^{-1/2} via Newton-Schulz with quad-shuffled
//   4x4 matmuls; store Z row; emit diag output block (coalesced).
// ---------------------------------------------------------------------------
__global__ void k_nodes(float* __restrict__ out, int N, long long L) {
    int t = blockIdx.x * blockDim.x + threadIdx.x;
    int n = t >> 2, a = t & 3;
    if (n >= N) return;

    float4 a0 = reinterpret_cast<const float4*>(g_diag)[(size_t)n * 4 + a]; // A0 row a
    float4 arow = a0;
    arow.x += (a == 0) ? 1.f : 0.f;
    arow.y += (a == 1) ? 1.f : 0.f;
    arow.z += (a == 2) ? 1.f : 0.f;
    arow.w += (a == 3) ? 1.f : 0.f;

    // trace: quad-sum of own diagonal element
    float d = pick(arow, a);
    float tr = d;
    tr += __shfl_xor_sync(0xffffffffu, tr, 1, 4);
    tr += __shfl_xor_sync(0xffffffffu, tr, 2, 4);
    // Gershgorin: quad-max of row abs-sums
    float g = fabsf(arow.x) + fabsf(arow.y) + fabsf(arow.z) + fabsf(arow.w);
    g = fmaxf(g, __shfl_xor_sync(0xffffffffu, g, 1, 4));
    g = fmaxf(g, __shfl_xor_sync(0xffffffffu, g, 2, 4));

    float s = fminf(tr, g);
    float inv_s = 1.f / s;

    float4 ya = make_float4(arow.x * inv_s, arow.y * inv_s, arow.z * inv_s, arow.w * inv_s);
    float4 za = make_float4((a == 0) ? 1.f : 0.f, (a == 1) ? 1.f : 0.f,
                            (a == 2) ? 1.f : 0.f, (a == 3) ? 1.f : 0.f);

#pragma unroll
    for (int it = 0; it < 14; it++) {
        // T row a = Z[a,:] * Y  (shuffle Y rows)
        float4 trow = make_float4(0.f, 0.f, 0.f, 0.f);
        trow = f4_fma(za.x, shfl4(ya, 0), trow);
        trow = f4_fma(za.y, shfl4(ya, 1), trow);
        trow = f4_fma(za.z, shfl4(ya, 2), trow);
        trow = f4_fma(za.w, shfl4(ya, 3), trow);
        // T = 1.5 I - 0.5 T
        trow.x = fmaf(-0.5f, trow.x, (a == 0) ? 1.5f : 0.f);
        trow.y = fmaf(-0.5f, trow.y, (a == 1) ? 1.5f : 0.f);
        trow.z = fmaf(-0.5f, trow.z, (a == 2) ? 1.5f : 0.f);
        trow.w = fmaf(-0.5f, trow.w, (a == 3) ? 1.5f : 0.f);
        // Yn row a = Y[a,:] * T ; Zn row a = T[a,:] * Z
        float4 yn = make_float4(0.f, 0.f, 0.f, 0.f);
        float4 zn = yn;
        yn = f4_fma(ya.x, shfl4(trow, 0), yn);
        yn = f4_fma(ya.y, shfl4(trow, 1), yn);
        yn = f4_fma(ya.z, shfl4(trow, 2), yn);
        yn = f4_fma(ya.w, shfl4(trow, 3), yn);
        zn = f4_fma(trow.x, shfl4(za, 0), zn);
        zn = f4_fma(trow.y, shfl4(za, 1), zn);
        zn = f4_fma(trow.z, shfl4(za, 2), zn);
        zn = f4_fma(trow.w, shfl4(za, 3), zn);
        ya = yn; za = zn;
    }

    float rs = rsqrtf(s);
    za = make_float4(za.x * rs, za.y * rs, za.z * rs, za.w * rs);  // Z row a

    reinterpret_cast<float4*>(g_invs)[(size_t)n * 4 + a] = za;

    // D row a = clip( Z[a,:] * A0 * Z )
    float4 w = make_float4(0.f, 0.f, 0.f, 0.f);
    w = f4_fma(za.x, shfl4(a0, 0), w);
    w = f4_fma(za.y, shfl4(a0, 1), w);
    w = f4_fma(za.z, shfl4(a0, 2), w);
    w = f4_fma(za.w, shfl4(a0, 3), w);
    float4 drow = make_float4(0.f, 0.f, 0.f, 0.f);
    drow = f4_fma(w.x, shfl4(za, 0), drow);
    drow = f4_fma(w.y, shfl4(za, 1), drow);
    drow = f4_fma(w.z, shfl4(za, 2), drow);
    drow = f4_fma(w.w, shfl4(za, 3), drow);
    drow = clip4(drow);

    float4* o = reinterpret_cast<float4*>(out);
    size_t L4 = (size_t)L >> 2;
    size_t idx = (size_t)n * 4 + a;
    float nb = (float)(n * 4);
    float ra = nb + (float)a;
    __stcs(o + idx,          make_float4(ra, ra, ra, ra));                   // rows
    __stcs(o + L4 + idx,     make_float4(nb, nb + 1.f, nb + 2.f, nb + 3.f)); // cols
    __stcs(o + 2 * L4 + idx, drow);                                          // vals
}

// ---------------------------------------------------------------------------
// Kernel 3 (fused emit, quad-shuffle): thread (e, a) loads only row a of
// P, Zi, Zj. T row a = (Zi[a,:]·P)·Zj via shuffled rows; T^T row a obtained
// by a 4x4 quad transpose of the clipped trow. Emits all 6 output float4s.
// ---------------------------------------------------------------------------
__global__ void k_emit(float* __restrict__ out,
                       const int* __restrict__ ei0,
                       int E, int N, long long L) {
    int t = blockIdx.x * blockDim.x + threadIdx.x;
    int e = t >> 2, a = t & 3;
    if (e >= E) return;

    int r = ei0[e];
    int c = ei0[E + e];

    float4 Pa  = __ldcs(reinterpret_cast<const float4*>(g_triu) + (size_t)e * 4 + a);
    float4 zia = __ldg(reinterpret_cast<const float4*>(g_invs) + (size_t)r * 4 + a);
    float4 zja = __ldg(reinterpret_cast<const float4*>(g_invs) + (size_t)c * 4 + a);

    // w = Zi[a,:] * P
    float4 w = make_float4(0.f, 0.f, 0.f, 0.f);
    w = f4_fma(zia.x, shfl4(Pa, 0), w);
    w = f4_fma(zia.y, shfl4(Pa, 1), w);
    w = f4_fma(zia.z, shfl4(Pa, 2), w);
    w = f4_fma(zia.w, shfl4(Pa, 3), w);
    // trow = w * Zj
    float4 trow = make_float4(0.f, 0.f, 0.f, 0.f);
    trow = f4_fma(w.x, shfl4(zja, 0), trow);
    trow = f4_fma(w.y, shfl4(zja, 1), trow);
    trow = f4_fma(w.z, shfl4(zja, 2), trow);
    trow = f4_fma(w.w, shfl4(zja, 3), trow);
    float4 tc = clip4(trow);

    // tcol[j] = clipped T[j][a] (quad transpose)
    float4 tcol;
    tcol.x = pick(shfl4(tc, 0), a);
    tcol.y = pick(shfl4(tc, 1), a);
    tcol.z = pick(shfl4(tc, 2), a);
    tcol.w = pick(shfl4(tc, 3), a);

    float4* o = reinterpret_cast<float4*>(out);
    size_t L4 = (size_t)L >> 2;
    size_t ij = (size_t)N * 4 + (size_t)e * 4 + a;
    size_t ji = ij + (size_t)E * 4;

    float rb = (float)(r * 4);
    float cb = (float)(c * 4);
    float ra = rb + (float)a;
    float ca = cb + (float)a;

    __stcs(o + ij,          make_float4(ra, ra, ra, ra));                   // rows ij
    __stcs(o + L4 + ij,     make_float4(cb, cb + 1.f, cb + 2.f, cb + 3.f)); // cols ij
    __stcs(o + 2 * L4 + ij, neg4(tc));                                      // vals ij
    __stcs(o + ji,          make_float4(ca, ca, ca, ca));                   // rows ji
    __stcs(o + L4 + ji,     make_float4(rb, rb + 1.f, rb + 2.f, rb + 3.f)); // cols ji
    __stcs(o + 2 * L4 + ji, neg4(tcol));                                    // vals ji
}

// ---------------------------------------------------------------------------
extern "C" void kernel_launch(void* const* d_in, const int* in_sizes, int n_in,
                              void* d_out, int out_size) {
    const float* maps = (const float*)d_in[0];
    const int*   ei   = (const int*)d_in[1];
    float*       out  = (float*)d_out;

    int twoE = in_sizes[0] / 16;           // 2E
    int E    = twoE / 2;
    long long L = (long long)out_size / 3; // entries per index array
    int N = (int)(L / 16 - twoE);

    int n4 = N * 4;
    int qe = E * 4;
    int qn = N * 4;
    k_zero_diag<<<(n4 + 255) / 256, 256>>>(n4);
    k_edges<<<(qe + 255) / 256, 256>>>(maps, ei, E);
    k_nodes<<<(qn + 255) / 256, 256>>>(out, N, L);
    k_emit <<<(qe + 255) / 256, 256>>>(out, ei, E, N, L);
}